// round 4
// baseline (speedup 1.0000x reference)
#include <cuda_runtime.h>
#include <cuda_bf16.h>
#include <cstdint>

#define BATCH 16
#define IC    512
#define OC    512
#define WD    512
#define HIN   32
#define RES   64
#define YS    65

#define MM   1024            // spatial positions per sample (32*32)
#define KK   512             // IC
#define NN   4608            // OC * 9 taps
#define MF   (BATCH * MM)    // flattened M = 16384

// GEMM tiling
#define TM   256
#define TN   128
#define TKC  64              // k per chunk (64 bf16 = 128B rows, swizzled)
#define NKC  (KK / TKC)      // 8 chunks

// ---------------- device scratch (static: no runtime allocation) -----------
__device__ float g_styles[BATCH * IC];
__device__ float g_dcoef [BATCH * OC];
__device__ float g_wsum  [OC * IC];
__device__ __nv_bfloat16 g_Ah[(size_t)MF * KK];           // 16MB  A hi  [bm][k]
__device__ __nv_bfloat16 g_Al[(size_t)MF * KK];           // 16MB  A lo
__device__ __nv_bfloat16 g_Bh[(size_t)NN * KK];           // 4.5MB B hi  [n][k]
__device__ __nv_bfloat16 g_Bl[(size_t)NN * KK];           // 4.5MB B lo
__device__ float g_ct[(size_t)BATCH * NN * MM];           // 302MB C^T  [b][n][m]

// ---------------- helpers ----------------------------------------------------
__device__ __forceinline__ uint32_t smem_u32(const void* p) {
    uint32_t a;
    asm("{ .reg .u64 t; cvta.to.shared.u64 t, %1; cvt.u32.u64 %0, t; }"
        : "=r"(a) : "l"(p));
    return a;
}

__device__ __forceinline__ void cp16(uint32_t saddr, const void* g) {
    asm volatile("cp.async.cg.shared.global [%0], [%1], 16;"
                 :: "r"(saddr), "l"(g) : "memory");
}

__device__ __forceinline__ void ldsm4(uint32_t* r, uint32_t addr) {
    asm volatile("ldmatrix.sync.aligned.m8n8.x4.shared.b16 {%0,%1,%2,%3}, [%4];"
                 : "=r"(r[0]), "=r"(r[1]), "=r"(r[2]), "=r"(r[3]) : "r"(addr));
}

__device__ __forceinline__ void mma_bf16(float* d, const uint32_t* a,
                                         uint32_t b0, uint32_t b1) {
    asm volatile(
        "mma.sync.aligned.m16n8k16.row.col.f32.bf16.bf16.f32 "
        "{%0,%1,%2,%3}, {%4,%5,%6,%7}, {%8,%9}, {%0,%1,%2,%3};"
        : "+f"(d[0]), "+f"(d[1]), "+f"(d[2]), "+f"(d[3])
        : "r"(a[0]), "r"(a[1]), "r"(a[2]), "r"(a[3]), "r"(b0), "r"(b1));
}

// SMEM layout: per stage 96KB = A(hi,lo) 64KB + B(hi,lo) 32KB; 2 stages = 192KB
#define SA(st, part)   ((st) * 98304u + (part) * 32768u)
#define SBB(st, part)  ((st) * 98304u + 65536u + (part) * 16384u)
#define SM_TOTAL_G     196608u

// ---------------------------------------------------------------------------
// K1: styles[b,ic]
// ---------------------------------------------------------------------------
__global__ void k_styles(const float* __restrict__ w,
                         const float* __restrict__ aw,
                         const float* __restrict__ ab) {
    int b = blockIdx.y, warp = threadIdx.x >> 5, lane = threadIdx.x & 31;
    int ic = blockIdx.x * 8 + warp;
    const float* wrow = w  + (size_t)b  * WD;
    const float* arow = aw + (size_t)ic * WD;
    float s = 0.f;
    #pragma unroll 4
    for (int k = lane; k < WD; k += 32) s += wrow[k] * arow[k];
    #pragma unroll
    for (int o = 16; o; o >>= 1) s += __shfl_xor_sync(0xffffffffu, s, o);
    if (lane == 0)
        g_styles[b * IC + ic] = s * 0.04419417382415922f + ab[ic];
}

// ---------------------------------------------------------------------------
// K2: wsum[oc,ic] = sum_{3x3} w^2
// ---------------------------------------------------------------------------
__global__ void k_wsum(const float* __restrict__ cw) {
    int idx = blockIdx.x * blockDim.x + threadIdx.x;
    if (idx >= OC * IC) return;
    const float* p = cw + (size_t)idx * 9;
    float s = 0.f;
    #pragma unroll
    for (int k = 0; k < 9; k++) { float v = p[k]; s += v * v; }
    g_wsum[idx] = s;
}

// ---------------------------------------------------------------------------
// K3: dcoef[b,oc]
// ---------------------------------------------------------------------------
__global__ void k_dcoef() {
    int b = blockIdx.y, warp = threadIdx.x >> 5, lane = threadIdx.x & 31;
    int oc = blockIdx.x * 8 + warp;
    float s = 0.f;
    #pragma unroll 4
    for (int ic = lane; ic < IC; ic += 32) {
        float st = g_styles[b * IC + ic];
        s += st * st * g_wsum[oc * IC + ic];
    }
    #pragma unroll
    for (int o = 16; o; o >>= 1) s += __shfl_xor_sync(0xffffffffu, s, o);
    if (lane == 0) g_dcoef[b * OC + oc] = rsqrtf(s + 1e-8f);
}

// ---------------------------------------------------------------------------
// K4: A prep — x[b][ic][m] -> A[b*1024+m][k], style-scaled, bf16 hi/lo split
// ---------------------------------------------------------------------------
__global__ void k_prepA(const float* __restrict__ x) {
    __shared__ float s[64][65];
    int b = blockIdx.z;
    int m0 = blockIdx.x * 64;
    int k0 = blockIdx.y * 64;
    int tid = threadIdx.x;
    for (int l = tid; l < 4096; l += 256) {
        int ii = l >> 6, jj = l & 63;
        float v = x[(((size_t)b * IC + k0 + ii) << 10) + m0 + jj]
                  * g_styles[b * IC + k0 + ii];
        s[jj][ii] = v;
    }
    __syncthreads();
    for (int l = tid; l < 4096; l += 256) {
        int mm = l >> 6, kk = l & 63;
        float v = s[mm][kk];
        __nv_bfloat16 h = __float2bfloat16(v);
        float r = v - __bfloat162float(h);
        size_t idx = (((size_t)b * MM + m0 + mm) << 9) + k0 + kk;
        g_Ah[idx] = h;
        g_Al[idx] = __float2bfloat16(r);
    }
}

// ---------------------------------------------------------------------------
// K5: B prep — cw[oc][ic][tap] -> B[n=oc*9+tap][k=ic], bf16 hi/lo split
// ---------------------------------------------------------------------------
__global__ void k_prepB(const float* __restrict__ cw) {
    __shared__ float s[4608];
    int oc = blockIdx.x, tid = threadIdx.x;
    for (int l = tid; l < 4608; l += 256) s[l] = cw[(size_t)oc * 4608 + l];
    __syncthreads();
    for (int l = tid; l < 4608; l += 256) {
        int t = l / 512, k = l & 511;
        float v = s[k * 9 + t];
        __nv_bfloat16 h = __float2bfloat16(v);
        float r = v - __bfloat162float(h);
        size_t idx = (((size_t)oc * 9 + t) << 9) + k;
        g_Bh[idx] = h;
        g_Bl[idx] = __float2bfloat16(r);
    }
}

// ---------------------------------------------------------------------------
// K6: mma.sync GEMM, flattened: C^T[n][bm] = sum_k A[bm][k]*B[n][k].
// CTA 256x128, 16 warps (4m x 4n), warp tile 64x32, 3xbf16 split,
// 2-stage cp.async pipeline, phased A-fragments to stay under 128 regs.
// ---------------------------------------------------------------------------
__device__ __forceinline__ void load_chunk_g(uint32_t sb, int m0, int n0,
                                             int c, int st, int tid) {
    size_t kc0 = (size_t)c * TKC;
    #pragma unroll
    for (int i = 0; i < 8; i++) {          // A: 2 parts x 256 rows x 8 chunks
        int l = tid + i * 512;             // 0..4095
        int part = l >> 11, r = (l >> 3) & 255, ch = l & 7;
        const __nv_bfloat16* gp = (part ? g_Al : g_Ah)
            + (((size_t)(m0 + r)) << 9) + kc0 + ch * 8;
        cp16(sb + SA(st, part) + r * 128u + ((ch ^ (r & 7)) * 16u), gp);
    }
    #pragma unroll
    for (int i = 0; i < 4; i++) {          // B: 2 parts x 128 rows x 8 chunks
        int l = tid + i * 512;             // 0..2047
        int part = l >> 10, r = (l >> 3) & 127, ch = l & 7;
        const __nv_bfloat16* gp = (part ? g_Bl : g_Bh)
            + (((size_t)(n0 + r)) << 9) + kc0 + ch * 8;
        cp16(sb + SBB(st, part) + r * 128u + ((ch ^ (r & 7)) * 16u), gp);
    }
    asm volatile("cp.async.commit_group;" ::: "memory");
}

__global__ void __launch_bounds__(512, 1) k_gemm() {
    extern __shared__ char smem[];
    uint32_t sb = smem_u32(smem);
    int tid = threadIdx.x, wid = tid >> 5, lane = tid & 31;
    int n0 = blockIdx.x * TN;
    int m0 = blockIdx.y * TM;      // flat (b,m): 256 | 1024, so b fixed per CTA

    int wm0 = (wid >> 2) * 64;     // warp m offset
    int wn0 = (wid & 3) * 32;      // warp n offset

    int mat = lane >> 3, rr = lane & 7;
    int lr  = (mat & 1) * 8 + rr;
    int chi = mat >> 1;

    uint32_t arow = (uint32_t)(wm0 + lr);
    uint32_t brow = (uint32_t)(wn0 + lr);
    uint32_t aswz = arow & 7;
    uint32_t bswz = brow & 7;

    float acc[4][4][4];
    #pragma unroll
    for (int i = 0; i < 4; i++)
        #pragma unroll
        for (int j = 0; j < 4; j++)
            #pragma unroll
            for (int q = 0; q < 4; q++) acc[i][j][q] = 0.f;

    load_chunk_g(sb, m0, n0, 0, 0, tid);

    #pragma unroll 1
    for (int c = 0; c < NKC; c++) {
        int st = c & 1;
        if (c + 1 < NKC) load_chunk_g(sb, m0, n0, c + 1, st ^ 1, tid);
        if (c + 1 < NKC)
            asm volatile("cp.async.wait_group 1;" ::: "memory");
        else
            asm volatile("cp.async.wait_group 0;" ::: "memory");
        __syncthreads();

        #pragma unroll
        for (int s = 0; s < 4; s++) {
            uint32_t kchunk = (uint32_t)(2 * s + chi);
            uint32_t acol = ((kchunk ^ aswz) * 16u);
            uint32_t bcol = ((kchunk ^ bswz) * 16u);

            uint32_t bfh[2][4], bfl[2][4];
            #pragma unroll
            for (int nj2 = 0; nj2 < 2; nj2++) {
                ldsm4(bfh[nj2], sb + SBB(st, 0) + (brow + nj2 * 16u) * 128u + bcol);
                ldsm4(bfl[nj2], sb + SBB(st, 1) + (brow + nj2 * 16u) * 128u + bcol);
            }

            uint32_t af[4][4];
            #pragma unroll
            for (int mi = 0; mi < 4; mi++)
                ldsm4(af[mi], sb + SA(st, 0) + (arow + mi * 16u) * 128u + acol);

            // hi * hi  (16 independent chains)
            #pragma unroll
            for (int mi = 0; mi < 4; mi++)
                #pragma unroll
                for (int nj = 0; nj < 4; nj++)
                    mma_bf16(acc[mi][nj], af[mi],
                             bfh[nj >> 1][nj & 1], bfh[nj >> 1][(nj & 1) + 2]);
            // hi * lo
            #pragma unroll
            for (int mi = 0; mi < 4; mi++)
                #pragma unroll
                for (int nj = 0; nj < 4; nj++)
                    mma_bf16(acc[mi][nj], af[mi],
                             bfl[nj >> 1][nj & 1], bfl[nj >> 1][(nj & 1) + 2]);
            // reload A fragments as lo, then lo * hi
            #pragma unroll
            for (int mi = 0; mi < 4; mi++)
                ldsm4(af[mi], sb + SA(st, 1) + (arow + mi * 16u) * 128u + acol);
            #pragma unroll
            for (int mi = 0; mi < 4; mi++)
                #pragma unroll
                for (int nj = 0; nj < 4; nj++)
                    mma_bf16(acc[mi][nj], af[mi],
                             bfh[nj >> 1][nj & 1], bfh[nj >> 1][(nj & 1) + 2]);
        }
        __syncthreads();
    }

    // epilogue: store transposed to g_ct[b][n][m]
    int b    = m0 >> 10;
    int mloc = m0 & 1023;
    int g  = lane >> 2;
    int cq = (lane & 3) * 2;
    #pragma unroll
    for (int mi = 0; mi < 4; mi++) {
        #pragma unroll
        for (int nj = 0; nj < 4; nj++) {
            int nb = n0 + wn0 + nj * 8 + cq;
            int mb = mloc + wm0 + mi * 16 + g;
            float* d0 = g_ct + ((size_t)b * NN + nb) * MM + mb;
            d0[0]      = acc[mi][nj][0];
            d0[MM]     = acc[mi][nj][1];
            d0[8]      = acc[mi][nj][2];
            d0[MM + 8] = acc[mi][nj][3];
        }
    }
}

// ---------------------------------------------------------------------------
// K7: fused tap-gather (transpose-conv assembly) + upfirdn 4x4 + noise + bias
//     + lrelu*sqrt(2).  One block per (b, oc).
// ---------------------------------------------------------------------------
#define SMF_YT   36864u                  // after 9*1024 floats
#define SMF_FK   (SMF_YT + 18768u)       // after 68*69 floats
#define SM_TOTAL_F (SMF_FK + 64u)

__global__ void __launch_bounds__(256) k_fir(const float* __restrict__ f,
                                             const float* __restrict__ noise,
                                             const float* __restrict__ bias,
                                             float* __restrict__ out) {
    extern __shared__ char smemf[];
    float* sct = (float*)smemf;                    // [9][1024]
    float* yt  = (float*)(smemf + SMF_YT);         // [68][69]
    float* fk  = (float*)(smemf + SMF_FK);

    int z = blockIdx.x;
    int b = z >> 9;
    int oc = z & 511;
    int tid = threadIdx.x;

    if (tid < 16) fk[tid] = f[tid] * 4.0f;
    float dco = g_dcoef[b * OC + oc];

    const float* csrc = g_ct + ((size_t)b * NN + (size_t)oc * 9) * MM;
    for (int i = tid; i < 9 * MM; i += 256) sct[i] = csrc[i];
    __syncthreads();

    // y tile (65x65 valid) at yt[p+1][q+1]
    for (int idx = tid; idx < 68 * 68; idx += 256) {
        int r = idx / 68, cq = idx - (idx / 68) * 68;
        int p = r - 1, q = cq - 1;
        float s = 0.f;
        int ilo = (p & 1) ? 1 : 0, istep = (p & 1) ? 4 : 2;
        for (int i = ilo; i <= 2; i += istep) {
            int ph = p - i;
            if (ph < 0) continue;
            int h = ph >> 1;
            if (h >= HIN) continue;
            int jlo = (q & 1) ? 1 : 0, jstep = (q & 1) ? 4 : 2;
            for (int j = jlo; j <= 2; j += jstep) {
                int qw = q - j;
                if (qw < 0) continue;
                int w = qw >> 1;
                if (w >= HIN) continue;
                s += sct[(i * 3 + j) * MM + h * 32 + w];
            }
        }
        yt[r * 69 + cq] = s * dco;
    }
    __syncthreads();

    int u  = tid & 63;
    int v0 = (tid >> 6) * 16;

    float res[16];
    #pragma unroll
    for (int c = 0; c < 16; c++) res[c] = 0.f;

    #pragma unroll
    for (int a = 0; a < 4; a++) {
        float row[19];
        #pragma unroll
        for (int c = 0; c < 19; c++) row[c] = yt[(u + a) * 69 + v0 + c];
        #pragma unroll
        for (int e = 0; e < 4; e++) {
            float fv = fk[a * 4 + e];
            #pragma unroll
            for (int c = 0; c < 16; c++) res[c] += fv * row[c + e];
        }
    }

    float bs = bias[oc];
    float* orow = out + (((size_t)(b * OC + oc) * RES) + u) * RES + v0;
    #pragma unroll
    for (int c = 0; c < 16; c++) {
        float v = res[c] + noise[u * RES + v0 + c] + bs;
        v = (v > 0.f) ? v : 0.2f * v;
        orow[c] = v * 1.4142135623730951f;
    }
}

// ---------------------------------------------------------------------------
extern "C" void kernel_launch(void* const* d_in, const int* in_sizes, int n_in,
                              void* d_out, int out_size) {
    const float* x     = (const float*)d_in[0];
    const float* w     = (const float*)d_in[1];
    const float* aw    = (const float*)d_in[2];
    const float* ab    = (const float*)d_in[3];
    const float* cw    = (const float*)d_in[4];
    const float* bias  = (const float*)d_in[5];
    const float* noise = (const float*)d_in[6];
    const float* f     = (const float*)d_in[7];
    float* out = (float*)d_out;

    cudaFuncSetAttribute(k_gemm, cudaFuncAttributeMaxDynamicSharedMemorySize, SM_TOTAL_G);
    cudaFuncSetAttribute(k_fir,  cudaFuncAttributeMaxDynamicSharedMemorySize, SM_TOTAL_F);

    k_styles<<<dim3(64, 16), 256>>>(w, aw, ab);
    k_wsum  <<<dim3(1024),   256>>>(cw);
    k_dcoef <<<dim3(64, 16), 256>>>();
    k_prepA <<<dim3(16, 8, 16), 256>>>(x);
    k_prepB <<<dim3(512),    256>>>(cw);
    k_gemm  <<<dim3(NN / TN, MF / TM), 512, SM_TOTAL_G>>>();
    k_fir   <<<dim3(BATCH * OC), 256, SM_TOTAL_F>>>(f, noise, bias, out);
}

// round 5
// speedup vs baseline: 1.5551x; 1.5551x over previous
#include <cuda_runtime.h>
#include <cuda_fp16.h>
#include <cstdint>

#define BATCH 16
#define IC    512
#define OC    512
#define WD    512
#define HIN   32
#define RES   64
#define YS    65

#define MM   1024            // spatial positions per sample (32*32)
#define KK   512             // IC
#define NN   4608            // OC * 9 taps
#define MF   (BATCH * MM)    // flattened M = 16384

// GEMM tiling
#define TM   256
#define TN   128
#define TKC  64              // k per chunk (64 fp16 = 128B rows, swizzled)
#define NKC  (KK / TKC)      // 8 chunks

// ---------------- device scratch (static: no runtime allocation) -----------
__device__ float g_styles[BATCH * IC];
__device__ float g_dcoef [BATCH * OC];
__device__ float g_wsum  [OC * IC];
__device__ __half g_A[(size_t)MF * KK];                   // 16MB  A fp16 [bm][k]
__device__ __half g_B[(size_t)NN * KK];                   // 4.5MB B fp16 [n][k]
__device__ float g_ct[(size_t)BATCH * NN * MM];           // 302MB C^T  [b][n][m]

// ---------------- helpers ----------------------------------------------------
__device__ __forceinline__ uint32_t smem_u32(const void* p) {
    uint32_t a;
    asm("{ .reg .u64 t; cvta.to.shared.u64 t, %1; cvt.u32.u64 %0, t; }"
        : "=r"(a) : "l"(p));
    return a;
}

__device__ __forceinline__ void cp16(uint32_t saddr, const void* g) {
    asm volatile("cp.async.cg.shared.global [%0], [%1], 16;"
                 :: "r"(saddr), "l"(g) : "memory");
}

__device__ __forceinline__ void ldsm4(uint32_t* r, uint32_t addr) {
    asm volatile("ldmatrix.sync.aligned.m8n8.x4.shared.b16 {%0,%1,%2,%3}, [%4];"
                 : "=r"(r[0]), "=r"(r[1]), "=r"(r[2]), "=r"(r[3]) : "r"(addr));
}

__device__ __forceinline__ void mma_fp16(float* d, const uint32_t* a,
                                         uint32_t b0, uint32_t b1) {
    asm volatile(
        "mma.sync.aligned.m16n8k16.row.col.f32.f16.f16.f32 "
        "{%0,%1,%2,%3}, {%4,%5,%6,%7}, {%8,%9}, {%0,%1,%2,%3};"
        : "+f"(d[0]), "+f"(d[1]), "+f"(d[2]), "+f"(d[3])
        : "r"(a[0]), "r"(a[1]), "r"(a[2]), "r"(a[3]), "r"(b0), "r"(b1));
}

// SMEM layout: per stage 48KB = A 32KB + B 16KB; 2 stages = 96KB
#define SA(st)   ((st) * 49152u)
#define SBB(st)  ((st) * 49152u + 32768u)
#define SM_TOTAL_G  98304u

// ---------------------------------------------------------------------------
// K1: styles[b,ic]
// ---------------------------------------------------------------------------
__global__ void k_styles(const float* __restrict__ w,
                         const float* __restrict__ aw,
                         const float* __restrict__ ab) {
    int b = blockIdx.y, warp = threadIdx.x >> 5, lane = threadIdx.x & 31;
    int ic = blockIdx.x * 8 + warp;
    const float* wrow = w  + (size_t)b  * WD;
    const float* arow = aw + (size_t)ic * WD;
    float s = 0.f;
    #pragma unroll 4
    for (int k = lane; k < WD; k += 32) s += wrow[k] * arow[k];
    #pragma unroll
    for (int o = 16; o; o >>= 1) s += __shfl_xor_sync(0xffffffffu, s, o);
    if (lane == 0)
        g_styles[b * IC + ic] = s * 0.04419417382415922f + ab[ic];
}

// ---------------------------------------------------------------------------
// K2: wsum[oc,ic] = sum_{3x3} w^2
// ---------------------------------------------------------------------------
__global__ void k_wsum(const float* __restrict__ cw) {
    int idx = blockIdx.x * blockDim.x + threadIdx.x;
    if (idx >= OC * IC) return;
    const float* p = cw + (size_t)idx * 9;
    float s = 0.f;
    #pragma unroll
    for (int k = 0; k < 9; k++) { float v = p[k]; s += v * v; }
    g_wsum[idx] = s;
}

// ---------------------------------------------------------------------------
// K3: dcoef[b,oc]
// ---------------------------------------------------------------------------
__global__ void k_dcoef() {
    int b = blockIdx.y, warp = threadIdx.x >> 5, lane = threadIdx.x & 31;
    int oc = blockIdx.x * 8 + warp;
    float s = 0.f;
    #pragma unroll 4
    for (int ic = lane; ic < IC; ic += 32) {
        float st = g_styles[b * IC + ic];
        s += st * st * g_wsum[oc * IC + ic];
    }
    #pragma unroll
    for (int o = 16; o; o >>= 1) s += __shfl_xor_sync(0xffffffffu, s, o);
    if (lane == 0) g_dcoef[b * OC + oc] = rsqrtf(s + 1e-8f);
}

// ---------------------------------------------------------------------------
// K4: A prep — x[b][ic][m] -> A[b*1024+m][k], style-scaled, fp16
// ---------------------------------------------------------------------------
__global__ void k_prepA(const float* __restrict__ x) {
    __shared__ float s[64][65];
    int b = blockIdx.z;
    int m0 = blockIdx.x * 64;
    int k0 = blockIdx.y * 64;
    int tid = threadIdx.x;
    for (int l = tid; l < 4096; l += 256) {
        int ii = l >> 6, jj = l & 63;
        float v = x[(((size_t)b * IC + k0 + ii) << 10) + m0 + jj]
                  * g_styles[b * IC + k0 + ii];
        s[jj][ii] = v;
    }
    __syncthreads();
    for (int l = tid; l < 4096; l += 256) {
        int mm = l >> 6, kk = l & 63;
        size_t idx = (((size_t)b * MM + m0 + mm) << 9) + k0 + kk;
        g_A[idx] = __float2half_rn(s[mm][kk]);
    }
}

// ---------------------------------------------------------------------------
// K5: B prep — cw[oc][ic][tap] -> B[n=oc*9+tap][k=ic], fp16
// ---------------------------------------------------------------------------
__global__ void k_prepB(const float* __restrict__ cw) {
    __shared__ float s[4608];
    int oc = blockIdx.x, tid = threadIdx.x;
    for (int l = tid; l < 4608; l += 256) s[l] = cw[(size_t)oc * 4608 + l];
    __syncthreads();
    for (int l = tid; l < 4608; l += 256) {
        int t = l / 512, k = l & 511;
        size_t idx = (((size_t)oc * 9 + t) << 9) + k;
        g_B[idx] = __float2half_rn(s[k * 9 + t]);
    }
}

// ---------------------------------------------------------------------------
// K6: mma.sync fp16 GEMM, flattened: C^T[n][bm] = sum_k A[bm][k]*B[n][k].
// CTA 256x128, 16 warps (4m x 4n), warp tile 64x32, 2-stage cp.async pipeline.
// ---------------------------------------------------------------------------
__device__ __forceinline__ void load_chunk_g(uint32_t sb, int m0, int n0,
                                             int c, int st, int tid) {
    size_t kc0 = (size_t)c * TKC;
    #pragma unroll
    for (int i = 0; i < 4; i++) {          // A: 256 rows x 8 (16B) chunks
        int l = tid + i * 512;             // 0..2047
        int r = l >> 3, ch = l & 7;
        const __half* gp = g_A + (((size_t)(m0 + r)) << 9) + kc0 + ch * 8;
        cp16(sb + SA(st) + r * 128u + ((ch ^ (r & 7)) * 16u), gp);
    }
    #pragma unroll
    for (int i = 0; i < 2; i++) {          // B: 128 rows x 8 (16B) chunks
        int l = tid + i * 512;             // 0..1023
        int r = l >> 3, ch = l & 7;
        const __half* gp = g_B + (((size_t)(n0 + r)) << 9) + kc0 + ch * 8;
        cp16(sb + SBB(st) + r * 128u + ((ch ^ (r & 7)) * 16u), gp);
    }
    asm volatile("cp.async.commit_group;" ::: "memory");
}

__global__ void __launch_bounds__(512, 1) k_gemm() {
    extern __shared__ char smem[];
    uint32_t sb = smem_u32(smem);
    int tid = threadIdx.x, wid = tid >> 5, lane = tid & 31;
    int n0 = blockIdx.x * TN;
    int m0 = blockIdx.y * TM;      // flat (b,m): 256 | 1024, so b fixed per CTA

    int wm0 = (wid >> 2) * 64;     // warp m offset
    int wn0 = (wid & 3) * 32;      // warp n offset

    int mat = lane >> 3, rr = lane & 7;
    int lr  = (mat & 1) * 8 + rr;
    int chi = mat >> 1;

    uint32_t arow = (uint32_t)(wm0 + lr);
    uint32_t brow = (uint32_t)(wn0 + lr);
    uint32_t aswz = arow & 7;
    uint32_t bswz = brow & 7;

    float acc[4][4][4];
    #pragma unroll
    for (int i = 0; i < 4; i++)
        #pragma unroll
        for (int j = 0; j < 4; j++)
            #pragma unroll
            for (int q = 0; q < 4; q++) acc[i][j][q] = 0.f;

    load_chunk_g(sb, m0, n0, 0, 0, tid);

    #pragma unroll 1
    for (int c = 0; c < NKC; c++) {
        int st = c & 1;
        if (c + 1 < NKC) load_chunk_g(sb, m0, n0, c + 1, st ^ 1, tid);
        if (c + 1 < NKC)
            asm volatile("cp.async.wait_group 1;" ::: "memory");
        else
            asm volatile("cp.async.wait_group 0;" ::: "memory");
        __syncthreads();

        #pragma unroll
        for (int s = 0; s < 4; s++) {
            uint32_t kchunk = (uint32_t)(2 * s + chi);
            uint32_t acol = ((kchunk ^ aswz) * 16u);
            uint32_t bcol = ((kchunk ^ bswz) * 16u);

            uint32_t bf[2][4];
            #pragma unroll
            for (int nj2 = 0; nj2 < 2; nj2++)
                ldsm4(bf[nj2], sb + SBB(st) + (brow + nj2 * 16u) * 128u + bcol);

            uint32_t af[4][4];
            #pragma unroll
            for (int mi = 0; mi < 4; mi++)
                ldsm4(af[mi], sb + SA(st) + (arow + mi * 16u) * 128u + acol);

            #pragma unroll
            for (int mi = 0; mi < 4; mi++)
                #pragma unroll
                for (int nj = 0; nj < 4; nj++)
                    mma_fp16(acc[mi][nj], af[mi],
                             bf[nj >> 1][nj & 1], bf[nj >> 1][(nj & 1) + 2]);
        }
        __syncthreads();
    }

    // epilogue: store transposed to g_ct[b][n][m]
    int b    = m0 >> 10;
    int mloc = m0 & 1023;
    int g  = lane >> 2;
    int cq = (lane & 3) * 2;
    #pragma unroll
    for (int mi = 0; mi < 4; mi++) {
        #pragma unroll
        for (int nj = 0; nj < 4; nj++) {
            int nb = n0 + wn0 + nj * 8 + cq;
            int mb = mloc + wm0 + mi * 16 + g;
            float* d0 = g_ct + ((size_t)b * NN + nb) * MM + mb;
            d0[0]      = acc[mi][nj][0];
            d0[MM]     = acc[mi][nj][1];
            d0[8]      = acc[mi][nj][2];
            d0[MM + 8] = acc[mi][nj][3];
        }
    }
}

// ---------------------------------------------------------------------------
// K7: fused tap-gather (transpose-conv assembly) + upfirdn 4x4 + noise + bias
//     + lrelu*sqrt(2).  One block per (b, oc).
// ---------------------------------------------------------------------------
#define SMF_YT   36864u                  // after 9*1024 floats
#define SMF_FK   (SMF_YT + 18768u)       // after 68*69 floats
#define SM_TOTAL_F (SMF_FK + 64u)

__global__ void __launch_bounds__(256) k_fir(const float* __restrict__ f,
                                             const float* __restrict__ noise,
                                             const float* __restrict__ bias,
                                             float* __restrict__ out) {
    extern __shared__ char smemf[];
    float* sct = (float*)smemf;                    // [9][1024]
    float* yt  = (float*)(smemf + SMF_YT);         // [68][69]
    float* fk  = (float*)(smemf + SMF_FK);

    int z = blockIdx.x;
    int b = z >> 9;
    int oc = z & 511;
    int tid = threadIdx.x;

    if (tid < 16) fk[tid] = f[tid] * 4.0f;
    float dco = g_dcoef[b * OC + oc];

    const float* csrc = g_ct + ((size_t)b * NN + (size_t)oc * 9) * MM;
    for (int i = tid; i < 9 * MM; i += 256) sct[i] = csrc[i];
    __syncthreads();

    // y tile (65x65 valid) at yt[p+1][q+1]
    for (int idx = tid; idx < 68 * 68; idx += 256) {
        int r = idx / 68, cq = idx - (idx / 68) * 68;
        int p = r - 1, q = cq - 1;
        float s = 0.f;
        int ilo = (p & 1) ? 1 : 0, istep = (p & 1) ? 4 : 2;
        for (int i = ilo; i <= 2; i += istep) {
            int ph = p - i;
            if (ph < 0) continue;
            int h = ph >> 1;
            if (h >= HIN) continue;
            int jlo = (q & 1) ? 1 : 0, jstep = (q & 1) ? 4 : 2;
            for (int j = jlo; j <= 2; j += jstep) {
                int qw = q - j;
                if (qw < 0) continue;
                int w = qw >> 1;
                if (w >= HIN) continue;
                s += sct[(i * 3 + j) * MM + h * 32 + w];
            }
        }
        yt[r * 69 + cq] = s * dco;
    }
    __syncthreads();

    int u  = tid & 63;
    int v0 = (tid >> 6) * 16;

    float res[16];
    #pragma unroll
    for (int c = 0; c < 16; c++) res[c] = 0.f;

    #pragma unroll
    for (int a = 0; a < 4; a++) {
        float row[19];
        #pragma unroll
        for (int c = 0; c < 19; c++) row[c] = yt[(u + a) * 69 + v0 + c];
        #pragma unroll
        for (int e = 0; e < 4; e++) {
            float fv = fk[a * 4 + e];
            #pragma unroll
            for (int c = 0; c < 16; c++) res[c] += fv * row[c + e];
        }
    }

    float bs = bias[oc];
    float* orow = out + (((size_t)(b * OC + oc) * RES) + u) * RES + v0;
    #pragma unroll
    for (int c = 0; c < 16; c++) {
        float v = res[c] + noise[u * RES + v0 + c] + bs;
        v = (v > 0.f) ? v : 0.2f * v;
        orow[c] = v * 1.4142135623730951f;
    }
}

// ---------------------------------------------------------------------------
extern "C" void kernel_launch(void* const* d_in, const int* in_sizes, int n_in,
                              void* d_out, int out_size) {
    const float* x     = (const float*)d_in[0];
    const float* w     = (const float*)d_in[1];
    const float* aw    = (const float*)d_in[2];
    const float* ab    = (const float*)d_in[3];
    const float* cw    = (const float*)d_in[4];
    const float* bias  = (const float*)d_in[5];
    const float* noise = (const float*)d_in[6];
    const float* f     = (const float*)d_in[7];
    float* out = (float*)d_out;

    cudaFuncSetAttribute(k_gemm, cudaFuncAttributeMaxDynamicSharedMemorySize, SM_TOTAL_G);
    cudaFuncSetAttribute(k_fir,  cudaFuncAttributeMaxDynamicSharedMemorySize, SM_TOTAL_F);

    // order chosen so k_gemm lands in the ncu capture slot (4th launch)
    k_styles<<<dim3(64, 16), 256>>>(w, aw, ab);
    k_prepA <<<dim3(16, 8, 16), 256>>>(x);
    k_prepB <<<dim3(512),    256>>>(cw);
    k_gemm  <<<dim3(NN / TN, MF / TM), 512, SM_TOTAL_G>>>();
    k_wsum  <<<dim3(1024),   256>>>(cw);
    k_dcoef <<<dim3(64, 16), 256>>>();
    k_fir   <<<dim3(BATCH * OC), 256, SM_TOTAL_F>>>(f, noise, bias, out);
}

// round 6
// speedup vs baseline: 1.6395x; 1.0543x over previous
#include <cuda_runtime.h>
#include <cuda_fp16.h>
#include <cstdint>

#define BATCH 16
#define IC    512
#define OC    512
#define WD    512
#define HIN   32
#define RES   64
#define YS    65

#define MM   1024            // spatial positions per sample (32*32)
#define KK   512             // IC
#define NN   4608            // OC * 9 taps
#define MF   (BATCH * MM)    // flattened M = 16384

// GEMM tiling
#define TM   256
#define TN   128
#define TKC  64              // k per chunk (64 fp16 = 128B rows, swizzled)
#define NKC  (KK / TKC)      // 8 chunks

// ---------------- device scratch (static: no runtime allocation) -----------
__device__ float g_styles[BATCH * IC];
__device__ float g_wsum  [OC * IC];
__device__ __half g_A[(size_t)MF * KK];                   // 16MB  A fp16 [bm][k]
__device__ __half g_B[(size_t)NN * KK];                   // 4.5MB B fp16 [n][k]
__device__ __half g_ct[(size_t)BATCH * NN * MM];          // 151MB C^T  [b][n][m]

// ---------------- helpers ----------------------------------------------------
__device__ __forceinline__ uint32_t smem_u32(const void* p) {
    uint32_t a;
    asm("{ .reg .u64 t; cvta.to.shared.u64 t, %1; cvt.u32.u64 %0, t; }"
        : "=r"(a) : "l"(p));
    return a;
}

__device__ __forceinline__ void cp16(uint32_t saddr, const void* g) {
    asm volatile("cp.async.cg.shared.global [%0], [%1], 16;"
                 :: "r"(saddr), "l"(g) : "memory");
}

__device__ __forceinline__ void ldsm4(uint32_t* r, uint32_t addr) {
    asm volatile("ldmatrix.sync.aligned.m8n8.x4.shared.b16 {%0,%1,%2,%3}, [%4];"
                 : "=r"(r[0]), "=r"(r[1]), "=r"(r[2]), "=r"(r[3]) : "r"(addr));
}

__device__ __forceinline__ void mma_fp16(float* d, const uint32_t* a,
                                         uint32_t b0, uint32_t b1) {
    asm volatile(
        "mma.sync.aligned.m16n8k16.row.col.f32.f16.f16.f32 "
        "{%0,%1,%2,%3}, {%4,%5,%6,%7}, {%8,%9}, {%0,%1,%2,%3};"
        : "+f"(d[0]), "+f"(d[1]), "+f"(d[2]), "+f"(d[3])
        : "r"(a[0]), "r"(a[1]), "r"(a[2]), "r"(a[3]), "r"(b0), "r"(b1));
}

// SMEM layout: per stage 48KB = A 32KB + B 16KB; 3 stages = 144KB
#define SA(st)   ((st) * 49152u)
#define SBB(st)  ((st) * 49152u + 32768u)
#define SM_TOTAL_G  147456u

// ---------------------------------------------------------------------------
// K1: fused styles + wsum.
//   blocks [0,1024):  styles[b,ic] (one warp per (b,ic))
//   blocks [1024,2048): wsum[oc,ic] = sum_{3x3} cw^2
// ---------------------------------------------------------------------------
__global__ void k_sw(const float* __restrict__ w,
                     const float* __restrict__ aw,
                     const float* __restrict__ ab,
                     const float* __restrict__ cw) {
    int bx = blockIdx.x, tid = threadIdx.x;
    if (bx < 1024) {
        int b = bx >> 6, icg = bx & 63;
        int warp = tid >> 5, lane = tid & 31;
        int ic = icg * 8 + warp;
        const float* wrow = w  + (size_t)b  * WD;
        const float* arow = aw + (size_t)ic * WD;
        float s = 0.f;
        #pragma unroll 4
        for (int k = lane; k < WD; k += 32) s += wrow[k] * arow[k];
        #pragma unroll
        for (int o = 16; o; o >>= 1) s += __shfl_xor_sync(0xffffffffu, s, o);
        if (lane == 0)
            g_styles[b * IC + ic] = s * 0.04419417382415922f + ab[ic];
    } else {
        int idx = (bx - 1024) * 256 + tid;          // oc*IC+ic
        const float* p = cw + (size_t)idx * 9;
        float s = 0.f;
        #pragma unroll
        for (int k = 0; k < 9; k++) { float v = p[k]; s += v * v; }
        g_wsum[idx] = s;
    }
}

// ---------------------------------------------------------------------------
// K2: fused prep.
//   blocks [0,2048):  A part — x[b][ic][m] -> A[b*1024+m][k], style-scaled fp16
//   blocks [2048,2560): B part — cw[oc][ic][tap] -> B[oc*9+tap][ic], fp16
// ---------------------------------------------------------------------------
__global__ void k_prep(const float* __restrict__ x, const float* __restrict__ cw) {
    __shared__ float s[4680];           // max(64*65, 4608)
    int bx = blockIdx.x, tid = threadIdx.x;
    if (bx < 2048) {
        int b  = bx >> 7;
        int m0 = (bx & 15) * 64;
        int k0 = ((bx >> 4) & 7) * 64;
        for (int l = tid; l < 4096; l += 256) {
            int ii = l >> 6, jj = l & 63;
            s[jj * 65 + ii] = x[(((size_t)b * IC + k0 + ii) << 10) + m0 + jj]
                              * g_styles[b * IC + k0 + ii];
        }
        __syncthreads();
        for (int l = tid; l < 4096; l += 256) {
            int mm = l >> 6, kk = l & 63;
            size_t idx = (((size_t)b * MM + m0 + mm) << 9) + k0 + kk;
            g_A[idx] = __float2half_rn(s[mm * 65 + kk]);
        }
    } else {
        int oc = bx - 2048;
        for (int l = tid; l < 4608; l += 256) s[l] = cw[(size_t)oc * 4608 + l];
        __syncthreads();
        for (int l = tid; l < 4608; l += 256) {
            int t = l / 512, k = l & 511;
            size_t idx = (((size_t)oc * 9 + t) << 9) + k;
            g_B[idx] = __float2half_rn(s[k * 9 + t]);
        }
    }
}

// ---------------------------------------------------------------------------
// K3: mma.sync fp16 GEMM, flattened: C^T[n][bm] = sum_k A[bm][k]*B[n][k].
// CTA 256x128, 16 warps (4m x 4n), warp tile 64x32.
// 3-stage cp.async pipeline, ONE barrier per k-chunk. fp16 output.
// ---------------------------------------------------------------------------
__device__ __forceinline__ void load_chunk_g(uint32_t sb, int m0, int n0,
                                             int c, int st, int tid) {
    size_t kc0 = (size_t)c * TKC;
    #pragma unroll
    for (int i = 0; i < 4; i++) {          // A: 256 rows x 8 (16B) chunks
        int l = tid + i * 512;
        int r = l >> 3, ch = l & 7;
        const __half* gp = g_A + (((size_t)(m0 + r)) << 9) + kc0 + ch * 8;
        cp16(sb + SA(st) + r * 128u + ((ch ^ (r & 7)) * 16u), gp);
    }
    #pragma unroll
    for (int i = 0; i < 2; i++) {          // B: 128 rows x 8 (16B) chunks
        int l = tid + i * 512;
        int r = l >> 3, ch = l & 7;
        const __half* gp = g_B + (((size_t)(n0 + r)) << 9) + kc0 + ch * 8;
        cp16(sb + SBB(st) + r * 128u + ((ch ^ (r & 7)) * 16u), gp);
    }
    asm volatile("cp.async.commit_group;" ::: "memory");
}

__global__ void __launch_bounds__(512, 1) k_gemm() {
    extern __shared__ char smem[];
    uint32_t sb = smem_u32(smem);
    int tid = threadIdx.x, wid = tid >> 5, lane = tid & 31;
    int n0 = blockIdx.x * TN;
    int m0 = blockIdx.y * TM;      // flat (b,m): 256 | 1024, so b fixed per CTA

    int wm0 = (wid >> 2) * 64;
    int wn0 = (wid & 3) * 32;

    int mat = lane >> 3, rr = lane & 7;
    int lr  = (mat & 1) * 8 + rr;
    int chi = mat >> 1;

    uint32_t arow = (uint32_t)(wm0 + lr);
    uint32_t brow = (uint32_t)(wn0 + lr);
    uint32_t aswz = arow & 7;
    uint32_t bswz = brow & 7;

    float acc[4][4][4];
    #pragma unroll
    for (int i = 0; i < 4; i++)
        #pragma unroll
        for (int j = 0; j < 4; j++)
            #pragma unroll
            for (int q = 0; q < 4; q++) acc[i][j][q] = 0.f;

    load_chunk_g(sb, m0, n0, 0, 0, tid);
    load_chunk_g(sb, m0, n0, 1, 1, tid);

    #pragma unroll 1
    for (int c = 0; c < NKC; c++) {
        int st = c % 3;
        if (c < NKC - 1)
            asm volatile("cp.async.wait_group 1;" ::: "memory");
        else
            asm volatile("cp.async.wait_group 0;" ::: "memory");
        __syncthreads();   // chunk c visible to all; stage (c+2)%3 free (compute c-1 done)
        if (c + 2 < NKC) load_chunk_g(sb, m0, n0, c + 2, (c + 2) % 3, tid);

        #pragma unroll
        for (int s = 0; s < 4; s++) {
            uint32_t kchunk = (uint32_t)(2 * s + chi);
            uint32_t acol = ((kchunk ^ aswz) * 16u);
            uint32_t bcol = ((kchunk ^ bswz) * 16u);

            uint32_t bf[2][4];
            #pragma unroll
            for (int nj2 = 0; nj2 < 2; nj2++)
                ldsm4(bf[nj2], sb + SBB(st) + (brow + nj2 * 16u) * 128u + bcol);

            uint32_t af[4][4];
            #pragma unroll
            for (int mi = 0; mi < 4; mi++)
                ldsm4(af[mi], sb + SA(st) + (arow + mi * 16u) * 128u + acol);

            #pragma unroll
            for (int mi = 0; mi < 4; mi++)
                #pragma unroll
                for (int nj = 0; nj < 4; nj++)
                    mma_fp16(acc[mi][nj], af[mi],
                             bf[nj >> 1][nj & 1], bf[nj >> 1][(nj & 1) + 2]);
        }
    }

    // epilogue: fp16 store transposed to g_ct[b][n][m]
    int b    = m0 >> 10;
    int mloc = m0 & 1023;
    int g  = lane >> 2;
    int cq = (lane & 3) * 2;
    #pragma unroll
    for (int mi = 0; mi < 4; mi++) {
        #pragma unroll
        for (int nj = 0; nj < 4; nj++) {
            int nb = n0 + wn0 + nj * 8 + cq;
            int mb = mloc + wm0 + mi * 16 + g;
            __half* d0 = g_ct + ((size_t)b * NN + nb) * MM + mb;
            d0[0]      = __float2half_rn(acc[mi][nj][0]);
            d0[MM]     = __float2half_rn(acc[mi][nj][1]);
            d0[8]      = __float2half_rn(acc[mi][nj][2]);
            d0[MM + 8] = __float2half_rn(acc[mi][nj][3]);
        }
    }
}

// ---------------------------------------------------------------------------
// K4: fused dcoef + tap-gather + upfirdn 4x4 + noise + bias + lrelu*sqrt(2).
// One block per (b, oc). Static smem ~37.4KB.
// ---------------------------------------------------------------------------
__global__ void __launch_bounds__(256) k_fir(const float* __restrict__ f,
                                             const float* __restrict__ noise,
                                             const float* __restrict__ bias,
                                             float* __restrict__ out) {
    __shared__ __half sct[9 * MM];       // 18KB, fp16 taps
    __shared__ float yt[68 * 69];        // 18.7KB
    __shared__ float fk[16];
    __shared__ float red[8];
    __shared__ float s_dco;

    int z = blockIdx.x;
    int b = z >> 9;
    int oc = z & 511;
    int tid = threadIdx.x;

    if (tid < 16) fk[tid] = f[tid] * 4.0f;

    // load 9 tap rows (9216 halves) as uint4
    const uint4* csrc = (const uint4*)(g_ct + ((size_t)b * NN + (size_t)oc * 9) * MM);
    uint4* sdst = (uint4*)sct;
    #pragma unroll
    for (int i = tid; i < 1152; i += 256) sdst[i] = csrc[i];

    // dcoef reduction
    float part = 0.f;
    #pragma unroll
    for (int ic = tid; ic < IC; ic += 256) {
        float st = g_styles[b * IC + ic];
        part += st * st * g_wsum[oc * IC + ic];
    }
    #pragma unroll
    for (int o = 16; o; o >>= 1) part += __shfl_xor_sync(0xffffffffu, part, o);
    if ((tid & 31) == 0) red[tid >> 5] = part;
    __syncthreads();
    if (tid == 0) {
        float t = 0.f;
        #pragma unroll
        for (int i = 0; i < 8; i++) t += red[i];
        s_dco = rsqrtf(t + 1e-8f);
    }
    __syncthreads();
    float dco = s_dco;

    // y tile (65x65 valid) at yt[p+1][q+1]
    for (int idx = tid; idx < 68 * 68; idx += 256) {
        int r = idx / 68, cq = idx - (idx / 68) * 68;
        int p = r - 1, q = cq - 1;
        float s = 0.f;
        int ilo = (p & 1) ? 1 : 0, istep = (p & 1) ? 4 : 2;
        for (int i = ilo; i <= 2; i += istep) {
            int ph = p - i;
            if (ph < 0) continue;
            int h = ph >> 1;
            if (h >= HIN) continue;
            int jlo = (q & 1) ? 1 : 0, jstep = (q & 1) ? 4 : 2;
            for (int j = jlo; j <= 2; j += jstep) {
                int qw = q - j;
                if (qw < 0) continue;
                int w = qw >> 1;
                if (w >= HIN) continue;
                s += __half2float(sct[(i * 3 + j) * MM + h * 32 + w]);
            }
        }
        yt[r * 69 + cq] = s * dco;
    }
    __syncthreads();

    int u  = tid & 63;
    int v0 = (tid >> 6) * 16;

    float res[16];
    #pragma unroll
    for (int c = 0; c < 16; c++) res[c] = 0.f;

    #pragma unroll
    for (int a = 0; a < 4; a++) {
        float row[19];
        #pragma unroll
        for (int c = 0; c < 19; c++) row[c] = yt[(u + a) * 69 + v0 + c];
        #pragma unroll
        for (int e = 0; e < 4; e++) {
            float fv = fk[a * 4 + e];
            #pragma unroll
            for (int c = 0; c < 16; c++) res[c] += fv * row[c + e];
        }
    }

    float bs = bias[oc];
    float* orow = out + (((size_t)(b * OC + oc) * RES) + u) * RES + v0;
    #pragma unroll
    for (int c = 0; c < 16; c++) {
        float v = res[c] + noise[u * RES + v0 + c] + bs;
        v = (v > 0.f) ? v : 0.2f * v;
        orow[c] = v * 1.4142135623730951f;
    }
}

// ---------------------------------------------------------------------------
extern "C" void kernel_launch(void* const* d_in, const int* in_sizes, int n_in,
                              void* d_out, int out_size) {
    const float* x     = (const float*)d_in[0];
    const float* w     = (const float*)d_in[1];
    const float* aw    = (const float*)d_in[2];
    const float* ab    = (const float*)d_in[3];
    const float* cw    = (const float*)d_in[4];
    const float* bias  = (const float*)d_in[5];
    const float* noise = (const float*)d_in[6];
    const float* f     = (const float*)d_in[7];
    float* out = (float*)d_out;

    cudaFuncSetAttribute(k_gemm, cudaFuncAttributeMaxDynamicSharedMemorySize, SM_TOTAL_G);

    k_sw   <<<2048, 256>>>(w, aw, ab, cw);
    k_prep <<<2560, 256>>>(x, cw);
    k_gemm <<<dim3(NN / TN, MF / TM), 512, SM_TOTAL_G>>>();
    k_fir  <<<BATCH * OC, 256>>>(f, noise, bias, out);
}

// round 8
// speedup vs baseline: 1.7455x; 1.0646x over previous
#include <cuda_runtime.h>
#include <cuda_fp16.h>
#include <cstdint>

#define BATCH 16
#define IC    512
#define OC    512
#define WD    512
#define HIN   32
#define RES   64
#define YS    65

#define MM   1024            // spatial positions per sample (32*32)
#define KK   512             // IC
#define NN   4608            // OC * 9 taps
#define MF   (BATCH * MM)    // flattened M = 16384

// GEMM tiling
#define TM   256
#define TN   128
#define TKC  64              // k per chunk (64 fp16 = 128B rows, swizzled)
#define NKC  (KK / TKC)      // 8 chunks

// ---------------- device scratch (static: no runtime allocation) -----------
__device__ float g_styles[BATCH * IC];
__device__ float g_wsum  [OC * IC];
__device__ __half g_A[(size_t)MF * KK];                   // 16MB  A fp16 [bm][k]
__device__ __half g_B[(size_t)NN * KK];                   // 4.5MB B fp16 [n][k]
__device__ __half g_ct[(size_t)BATCH * NN * MM];          // 151MB C^T  [b][n][m]

// ---------------- helpers ----------------------------------------------------
__device__ __forceinline__ uint32_t smem_u32(const void* p) {
    uint32_t a;
    asm("{ .reg .u64 t; cvta.to.shared.u64 t, %1; cvt.u32.u64 %0, t; }"
        : "=r"(a) : "l"(p));
    return a;
}

__device__ __forceinline__ void cp16(uint32_t saddr, const void* g) {
    asm volatile("cp.async.cg.shared.global [%0], [%1], 16;"
                 :: "r"(saddr), "l"(g) : "memory");
}

__device__ __forceinline__ void ldsm4(uint32_t* r, uint32_t addr) {
    asm volatile("ldmatrix.sync.aligned.m8n8.x4.shared.b16 {%0,%1,%2,%3}, [%4];"
                 : "=r"(r[0]), "=r"(r[1]), "=r"(r[2]), "=r"(r[3]) : "r"(addr));
}

__device__ __forceinline__ void mma_fp16(float* d, const uint32_t* a,
                                         uint32_t b0, uint32_t b1) {
    asm volatile(
        "mma.sync.aligned.m16n8k16.row.col.f32.f16.f16.f32 "
        "{%0,%1,%2,%3}, {%4,%5,%6,%7}, {%8,%9}, {%0,%1,%2,%3};"
        : "+f"(d[0]), "+f"(d[1]), "+f"(d[2]), "+f"(d[3])
        : "r"(a[0]), "r"(a[1]), "r"(a[2]), "r"(a[3]), "r"(b0), "r"(b1));
}

// SMEM layout: per stage 48KB = A 32KB + B 16KB; 3 stages = 144KB
#define SA(st)   ((st) * 49152u)
#define SBB(st)  ((st) * 49152u + 32768u)
#define SM_TOTAL_G  147456u

// ---------------------------------------------------------------------------
// K1: fused styles + wsum.
// ---------------------------------------------------------------------------
__global__ void k_sw(const float* __restrict__ w,
                     const float* __restrict__ aw,
                     const float* __restrict__ ab,
                     const float* __restrict__ cw) {
    int bx = blockIdx.x, tid = threadIdx.x;
    if (bx < 1024) {
        int b = bx >> 6, icg = bx & 63;
        int warp = tid >> 5, lane = tid & 31;
        int ic = icg * 8 + warp;
        const float* wrow = w  + (size_t)b  * WD;
        const float* arow = aw + (size_t)ic * WD;
        float s = 0.f;
        #pragma unroll 4
        for (int k = lane; k < WD; k += 32) s += wrow[k] * arow[k];
        #pragma unroll
        for (int o = 16; o; o >>= 1) s += __shfl_xor_sync(0xffffffffu, s, o);
        if (lane == 0)
            g_styles[b * IC + ic] = s * 0.04419417382415922f + ab[ic];
    } else {
        int idx = (bx - 1024) * 256 + tid;          // oc*IC+ic
        const float* p = cw + (size_t)idx * 9;
        float s = 0.f;
        #pragma unroll
        for (int k = 0; k < 9; k++) { float v = p[k]; s += v * v; }
        g_wsum[idx] = s;
    }
}

// ---------------------------------------------------------------------------
// K2: fused prep (A style-scaled fp16 transpose; B fp16 reorder)
// ---------------------------------------------------------------------------
__global__ void k_prep(const float* __restrict__ x, const float* __restrict__ cw) {
    __shared__ float s[4680];           // max(64*65, 4608)
    int bx = blockIdx.x, tid = threadIdx.x;
    if (bx < 2048) {
        int b  = bx >> 7;
        int m0 = (bx & 15) * 64;
        int k0 = ((bx >> 4) & 7) * 64;
        for (int l = tid; l < 4096; l += 256) {
            int ii = l >> 6, jj = l & 63;
            s[jj * 65 + ii] = x[(((size_t)b * IC + k0 + ii) << 10) + m0 + jj]
                              * g_styles[b * IC + k0 + ii];
        }
        __syncthreads();
        for (int l = tid; l < 4096; l += 256) {
            int mm = l >> 6, kk = l & 63;
            size_t idx = (((size_t)b * MM + m0 + mm) << 9) + k0 + kk;
            g_A[idx] = __float2half_rn(s[mm * 65 + kk]);
        }
    } else {
        int oc = bx - 2048;
        for (int l = tid; l < 4608; l += 256) s[l] = cw[(size_t)oc * 4608 + l];
        __syncthreads();
        for (int l = tid; l < 4608; l += 256) {
            int t = l / 512, k = l & 511;
            size_t idx = (((size_t)oc * 9 + t) << 9) + k;
            g_B[idx] = __float2half_rn(s[k * 9 + t]);
        }
    }
}

// ---------------------------------------------------------------------------
// K3: mma.sync fp16 GEMM (unchanged): C^T[n][bm] = sum_k A[bm][k]*B[n][k]
// ---------------------------------------------------------------------------
__device__ __forceinline__ void load_chunk_g(uint32_t sb, int m0, int n0,
                                             int c, int st, int tid) {
    size_t kc0 = (size_t)c * TKC;
    #pragma unroll
    for (int i = 0; i < 4; i++) {
        int l = tid + i * 512;
        int r = l >> 3, ch = l & 7;
        const __half* gp = g_A + (((size_t)(m0 + r)) << 9) + kc0 + ch * 8;
        cp16(sb + SA(st) + r * 128u + ((ch ^ (r & 7)) * 16u), gp);
    }
    #pragma unroll
    for (int i = 0; i < 2; i++) {
        int l = tid + i * 512;
        int r = l >> 3, ch = l & 7;
        const __half* gp = g_B + (((size_t)(n0 + r)) << 9) + kc0 + ch * 8;
        cp16(sb + SBB(st) + r * 128u + ((ch ^ (r & 7)) * 16u), gp);
    }
    asm volatile("cp.async.commit_group;" ::: "memory");
}

__global__ void __launch_bounds__(512, 1) k_gemm() {
    extern __shared__ char smem[];
    uint32_t sb = smem_u32(smem);
    int tid = threadIdx.x, wid = tid >> 5, lane = tid & 31;
    int n0 = blockIdx.x * TN;
    int m0 = blockIdx.y * TM;

    int wm0 = (wid >> 2) * 64;
    int wn0 = (wid & 3) * 32;

    int mat = lane >> 3, rr = lane & 7;
    int lr  = (mat & 1) * 8 + rr;
    int chi = mat >> 1;

    uint32_t arow = (uint32_t)(wm0 + lr);
    uint32_t brow = (uint32_t)(wn0 + lr);
    uint32_t aswz = arow & 7;
    uint32_t bswz = brow & 7;

    float acc[4][4][4];
    #pragma unroll
    for (int i = 0; i < 4; i++)
        #pragma unroll
        for (int j = 0; j < 4; j++)
            #pragma unroll
            for (int q = 0; q < 4; q++) acc[i][j][q] = 0.f;

    load_chunk_g(sb, m0, n0, 0, 0, tid);
    load_chunk_g(sb, m0, n0, 1, 1, tid);

    #pragma unroll 1
    for (int c = 0; c < NKC; c++) {
        int st = c % 3;
        if (c < NKC - 1)
            asm volatile("cp.async.wait_group 1;" ::: "memory");
        else
            asm volatile("cp.async.wait_group 0;" ::: "memory");
        __syncthreads();
        if (c + 2 < NKC) load_chunk_g(sb, m0, n0, c + 2, (c + 2) % 3, tid);

        #pragma unroll
        for (int s = 0; s < 4; s++) {
            uint32_t kchunk = (uint32_t)(2 * s + chi);
            uint32_t acol = ((kchunk ^ aswz) * 16u);
            uint32_t bcol = ((kchunk ^ bswz) * 16u);

            uint32_t bf[2][4];
            #pragma unroll
            for (int nj2 = 0; nj2 < 2; nj2++)
                ldsm4(bf[nj2], sb + SBB(st) + (brow + nj2 * 16u) * 128u + bcol);

            uint32_t af[4][4];
            #pragma unroll
            for (int mi = 0; mi < 4; mi++)
                ldsm4(af[mi], sb + SA(st) + (arow + mi * 16u) * 128u + acol);

            #pragma unroll
            for (int mi = 0; mi < 4; mi++)
                #pragma unroll
                for (int nj = 0; nj < 4; nj++)
                    mma_fp16(acc[mi][nj], af[mi],
                             bf[nj >> 1][nj & 1], bf[nj >> 1][(nj & 1) + 2]);
        }
    }

    int b    = m0 >> 10;
    int mloc = m0 & 1023;
    int g  = lane >> 2;
    int cq = (lane & 3) * 2;
    #pragma unroll
    for (int mi = 0; mi < 4; mi++) {
        #pragma unroll
        for (int nj = 0; nj < 4; nj++) {
            int nb = n0 + wn0 + nj * 8 + cq;
            int mb = mloc + wm0 + mi * 16 + g;
            __half* d0 = g_ct + ((size_t)b * NN + nb) * MM + mb;
            d0[0]      = __float2half_rn(acc[mi][nj][0]);
            d0[MM]     = __float2half_rn(acc[mi][nj][1]);
            d0[8]      = __float2half_rn(acc[mi][nj][2]);
            d0[MM + 8] = __float2half_rn(acc[mi][nj][3]);
        }
    }
}

// ---------------------------------------------------------------------------
// K4: fused dcoef + (tap-gather ∘ upfirdn) + noise + bias + lrelu*sqrt2.
// out[u,v] = dco * Σ_{tap(i,j)} [ fk[a0][e]·c[hS] + fk[a0+2][e]·c[hS+1] ] terms
// with t=u-1-i, a0=t&1, hS=(t+a0)/2;  s=v-1-j, e0=s&1, wS=(s+e0)/2,
// coeff fk[.][e0] at wS, fk[.][e0+2] at wS+1.  (larger a/e -> larger h/w)
// One block per (b, oc). Planes zero-padded h∈[-2,32], w∈[-2,34], stride 37.
// ---------------------------------------------------------------------------
#define PR 35
#define PCS 37
__global__ void __launch_bounds__(256) k_fir(const float* __restrict__ f,
                                             const float* __restrict__ noise,
                                             const float* __restrict__ bias,
                                             float* __restrict__ out) {
    __shared__ float pl[9][PR][PCS];     // 46.6KB, zero-padded tap planes
    __shared__ float fk[16];
    __shared__ float red[8];
    __shared__ float s_dco;

    int z = blockIdx.x;
    int b = z >> 9;
    int oc = z & 511;
    int tid = threadIdx.x;

    if (tid < 16) fk[tid] = f[tid] * 4.0f;

    // zero planes
    float* plf = &pl[0][0][0];
    #pragma unroll
    for (int i = tid; i < 9 * PR * PCS; i += 256) plf[i] = 0.f;

    // dcoef partial (overlaps with zeroing)
    float part = 0.f;
    #pragma unroll
    for (int ic = tid; ic < IC; ic += 256) {
        float st = g_styles[b * IC + ic];
        part += st * st * g_wsum[oc * IC + ic];
    }
    #pragma unroll
    for (int o = 16; o; o >>= 1) part += __shfl_xor_sync(0xffffffffu, part, o);
    if ((tid & 31) == 0) red[tid >> 5] = part;
    __syncthreads();

    if (tid == 0) {
        float t = 0.f;
        #pragma unroll
        for (int i = 0; i < 8; i++) t += red[i];
        s_dco = rsqrtf(t + 1e-8f);
    }

    // fill plane interiors from g_ct (fp16, coalesced uint4 = 8 halves)
    const uint4* csrc = (const uint4*)(g_ct + ((size_t)b * NN + (size_t)oc * 9) * MM);
    for (int i = tid; i < 1152; i += 256) {
        uint4 v = csrc[i];
        int tap = i >> 7, rem = i & 127;
        int h = rem >> 2, wc = (rem & 3) * 8;
        float* dst = &pl[tap][h + 2][wc + 2];
        const __half2* hp = (const __half2*)&v;
        #pragma unroll
        for (int q = 0; q < 4; q++) {
            float2 f2 = __half22float2(hp[q]);
            dst[2 * q]     = f2.x;
            dst[2 * q + 1] = f2.y;
        }
    }
    __syncthreads();
    float dco = s_dco;

    int u  = tid & 63;
    int v0 = (tid >> 6) * 16;

    float res[16];
    #pragma unroll
    for (int c = 0; c < 16; c++) res[c] = 0.f;

    #pragma unroll
    for (int tap = 0; tap < 9; tap++) {
        const int i = tap / 3, j = tap % 3;
        int t  = u - 1 - i;
        int a0 = t & 1;
        int hS = (t - a0) / 2 + a0;               // (t + a0) >> 1, exact for t<0 too
        // row hS  -> fk row a0 ; row hS+1 -> fk row a0+2
        const float* rA = &pl[tap][hS + 2][2];
        const float* rB = &pl[tap][hS + 3][2];

        int s0 = v0 - 1 - j;
        int p0 = s0 & 1;
        int W0 = (s0 - p0) / 2 + p0;              // (s0 + p0) >> 1

        float rowA[10], rowB[10];
        #pragma unroll
        for (int l = 0; l < 10; l++) {
            rowA[l] = rA[W0 + l];
            rowB[l] = rB[W0 + l];
        }

        float fa0 = fk[a0 * 4 + 0], fa1 = fk[a0 * 4 + 1];
        float fa2 = fk[a0 * 4 + 2], fa3 = fk[a0 * 4 + 3];
        float fb0 = fk[(a0 + 2) * 4 + 0], fb1 = fk[(a0 + 2) * 4 + 1];
        float fb2 = fk[(a0 + 2) * 4 + 2], fb3 = fk[(a0 + 2) * 4 + 3];

        if (p0 == 0) {
            // even v (e0=0): fk[.][0]@[k], fk[.][2]@[k+1]
            // odd  v (e0=1): fk[.][1]@[k+1], fk[.][3]@[k+2]
            #pragma unroll
            for (int k = 0; k < 8; k++) {
                res[2*k]   += fa0 * rowA[k]     + fa2 * rowA[k + 1]
                            + fb0 * rowB[k]     + fb2 * rowB[k + 1];
                res[2*k+1] += fa1 * rowA[k + 1] + fa3 * rowA[k + 2]
                            + fb1 * rowB[k + 1] + fb3 * rowB[k + 2];
            }
        } else {
            // even v (e0=1): fk[.][1]@[k], fk[.][3]@[k+1]
            // odd  v (e0=0): fk[.][0]@[k], fk[.][2]@[k+1]
            #pragma unroll
            for (int k = 0; k < 8; k++) {
                res[2*k]   += fa1 * rowA[k] + fa3 * rowA[k + 1]
                            + fb1 * rowB[k] + fb3 * rowB[k + 1];
                res[2*k+1] += fa0 * rowA[k] + fa2 * rowA[k + 1]
                            + fb0 * rowB[k] + fb2 * rowB[k + 1];
            }
        }
    }

    float bs = bias[oc];
    float* orow = out + (((size_t)(b * OC + oc) * RES) + u) * RES + v0;
    const float* nrow = noise + u * RES + v0;
    #pragma unroll
    for (int c = 0; c < 16; c++) {
        float v = res[c] * dco + nrow[c] + bs;
        v = (v > 0.f) ? v : 0.2f * v;
        orow[c] = v * 1.4142135623730951f;
    }
}

// ---------------------------------------------------------------------------
extern "C" void kernel_launch(void* const* d_in, const int* in_sizes, int n_in,
                              void* d_out, int out_size) {
    const float* x     = (const float*)d_in[0];
    const float* w     = (const float*)d_in[1];
    const float* aw    = (const float*)d_in[2];
    const float* ab    = (const float*)d_in[3];
    const float* cw    = (const float*)d_in[4];
    const float* bias  = (const float*)d_in[5];
    const float* noise = (const float*)d_in[6];
    const float* f     = (const float*)d_in[7];
    float* out = (float*)d_out;

    cudaFuncSetAttribute(k_gemm, cudaFuncAttributeMaxDynamicSharedMemorySize, SM_TOTAL_G);

    k_sw   <<<2048, 256>>>(w, aw, ab, cw);
    k_prep <<<2560, 256>>>(x, cw);
    k_gemm <<<dim3(NN / TN, MF / TM), 512, SM_TOTAL_G>>>();
    k_fir  <<<BATCH * OC, 256>>>(f, noise, bias, out);
}

// round 9
// speedup vs baseline: 1.7642x; 1.0107x over previous
#include <cuda_runtime.h>
#include <cuda_fp16.h>
#include <cstdint>

#define BATCH 16
#define IC    512
#define OC    512
#define WD    512
#define HIN   32
#define RES   64
#define YS    65

#define MM   1024            // spatial positions per sample (32*32)
#define KK   512             // IC
#define NN   4608            // OC * 9 taps
#define MF   (BATCH * MM)    // flattened M = 16384

// GEMM tiling
#define TM   256
#define TN   128
#define TKC  64              // k per chunk (64 fp16 = 128B rows, swizzled)
#define NKC  (KK / TKC)      // 8 chunks

// ---------------- device scratch (static: no runtime allocation) -----------
__device__ float g_styles[BATCH * IC];
__device__ float g_wsum  [OC * IC];
__device__ __half g_A[(size_t)MF * KK];                   // 16MB  A fp16 [bm][k]
__device__ __half g_B[(size_t)NN * KK];                   // 4.5MB B fp16 [n][k]
__device__ __half g_ct[(size_t)BATCH * NN * MM];          // 151MB C^T  [b][n][m]

// ---------------- helpers ----------------------------------------------------
__device__ __forceinline__ uint32_t smem_u32(const void* p) {
    uint32_t a;
    asm("{ .reg .u64 t; cvta.to.shared.u64 t, %1; cvt.u32.u64 %0, t; }"
        : "=r"(a) : "l"(p));
    return a;
}

__device__ __forceinline__ void cp16(uint32_t saddr, const void* g) {
    asm volatile("cp.async.cg.shared.global [%0], [%1], 16;"
                 :: "r"(saddr), "l"(g) : "memory");
}

__device__ __forceinline__ void ldsm4(uint32_t* r, uint32_t addr) {
    asm volatile("ldmatrix.sync.aligned.m8n8.x4.shared.b16 {%0,%1,%2,%3}, [%4];"
                 : "=r"(r[0]), "=r"(r[1]), "=r"(r[2]), "=r"(r[3]) : "r"(addr));
}

__device__ __forceinline__ void mma_fp16(float* d, const uint32_t* a,
                                         uint32_t b0, uint32_t b1) {
    asm volatile(
        "mma.sync.aligned.m16n8k16.row.col.f32.f16.f16.f32 "
        "{%0,%1,%2,%3}, {%4,%5,%6,%7}, {%8,%9}, {%0,%1,%2,%3};"
        : "+f"(d[0]), "+f"(d[1]), "+f"(d[2]), "+f"(d[3])
        : "r"(a[0]), "r"(a[1]), "r"(a[2]), "r"(a[3]), "r"(b0), "r"(b1));
}

// SMEM layout: per stage 48KB = A 32KB + B 16KB; 3 stages = 144KB
#define SA(st)   ((st) * 49152u)
#define SBB(st)  ((st) * 49152u + 32768u)
#define SM_TOTAL_G  147456u

// ---------------------------------------------------------------------------
// K1: fused styles + wsum.
// ---------------------------------------------------------------------------
__global__ void k_sw(const float* __restrict__ w,
                     const float* __restrict__ aw,
                     const float* __restrict__ ab,
                     const float* __restrict__ cw) {
    int bx = blockIdx.x, tid = threadIdx.x;
    if (bx < 1024) {
        int b = bx >> 6, icg = bx & 63;
        int warp = tid >> 5, lane = tid & 31;
        int ic = icg * 8 + warp;
        const float* wrow = w  + (size_t)b  * WD;
        const float* arow = aw + (size_t)ic * WD;
        float s = 0.f;
        #pragma unroll 4
        for (int k = lane; k < WD; k += 32) s += wrow[k] * arow[k];
        #pragma unroll
        for (int o = 16; o; o >>= 1) s += __shfl_xor_sync(0xffffffffu, s, o);
        if (lane == 0)
            g_styles[b * IC + ic] = s * 0.04419417382415922f + ab[ic];
    } else {
        int idx = (bx - 1024) * 256 + tid;          // oc*IC+ic
        const float* p = cw + (size_t)idx * 9;
        float s = 0.f;
        #pragma unroll
        for (int k = 0; k < 9; k++) { float v = p[k]; s += v * v; }
        g_wsum[idx] = s;
    }
}

// ---------------------------------------------------------------------------
// K2: fused prep (A style-scaled fp16 transpose; B fp16 reorder)
// ---------------------------------------------------------------------------
__global__ void k_prep(const float* __restrict__ x, const float* __restrict__ cw) {
    __shared__ float s[4680];           // max(64*65, 4608)
    int bx = blockIdx.x, tid = threadIdx.x;
    if (bx < 2048) {
        int b  = bx >> 7;
        int m0 = (bx & 15) * 64;
        int k0 = ((bx >> 4) & 7) * 64;
        for (int l = tid; l < 4096; l += 256) {
            int ii = l >> 6, jj = l & 63;
            s[jj * 65 + ii] = x[(((size_t)b * IC + k0 + ii) << 10) + m0 + jj]
                              * g_styles[b * IC + k0 + ii];
        }
        __syncthreads();
        for (int l = tid; l < 4096; l += 256) {
            int mm = l >> 6, kk = l & 63;
            size_t idx = (((size_t)b * MM + m0 + mm) << 9) + k0 + kk;
            g_A[idx] = __float2half_rn(s[mm * 65 + kk]);
        }
    } else {
        int oc = bx - 2048;
        for (int l = tid; l < 4608; l += 256) s[l] = cw[(size_t)oc * 4608 + l];
        __syncthreads();
        for (int l = tid; l < 4608; l += 256) {
            int t = l / 512, k = l & 511;
            size_t idx = (((size_t)oc * 9 + t) << 9) + k;
            g_B[idx] = __float2half_rn(s[k * 9 + t]);
        }
    }
}

// ---------------------------------------------------------------------------
// K3: mma.sync fp16 GEMM (unchanged): C^T[n][bm] = sum_k A[bm][k]*B[n][k]
// ---------------------------------------------------------------------------
__device__ __forceinline__ void load_chunk_g(uint32_t sb, int m0, int n0,
                                             int c, int st, int tid) {
    size_t kc0 = (size_t)c * TKC;
    #pragma unroll
    for (int i = 0; i < 4; i++) {
        int l = tid + i * 512;
        int r = l >> 3, ch = l & 7;
        const __half* gp = g_A + (((size_t)(m0 + r)) << 9) + kc0 + ch * 8;
        cp16(sb + SA(st) + r * 128u + ((ch ^ (r & 7)) * 16u), gp);
    }
    #pragma unroll
    for (int i = 0; i < 2; i++) {
        int l = tid + i * 512;
        int r = l >> 3, ch = l & 7;
        const __half* gp = g_B + (((size_t)(n0 + r)) << 9) + kc0 + ch * 8;
        cp16(sb + SBB(st) + r * 128u + ((ch ^ (r & 7)) * 16u), gp);
    }
    asm volatile("cp.async.commit_group;" ::: "memory");
}

__global__ void __launch_bounds__(512, 1) k_gemm() {
    extern __shared__ char smem[];
    uint32_t sb = smem_u32(smem);
    int tid = threadIdx.x, wid = tid >> 5, lane = tid & 31;
    int n0 = blockIdx.x * TN;
    int m0 = blockIdx.y * TM;

    int wm0 = (wid >> 2) * 64;
    int wn0 = (wid & 3) * 32;

    int mat = lane >> 3, rr = lane & 7;
    int lr  = (mat & 1) * 8 + rr;
    int chi = mat >> 1;

    uint32_t arow = (uint32_t)(wm0 + lr);
    uint32_t brow = (uint32_t)(wn0 + lr);
    uint32_t aswz = arow & 7;
    uint32_t bswz = brow & 7;

    float acc[4][4][4];
    #pragma unroll
    for (int i = 0; i < 4; i++)
        #pragma unroll
        for (int j = 0; j < 4; j++)
            #pragma unroll
            for (int q = 0; q < 4; q++) acc[i][j][q] = 0.f;

    load_chunk_g(sb, m0, n0, 0, 0, tid);
    load_chunk_g(sb, m0, n0, 1, 1, tid);

    #pragma unroll 1
    for (int c = 0; c < NKC; c++) {
        int st = c % 3;
        if (c < NKC - 1)
            asm volatile("cp.async.wait_group 1;" ::: "memory");
        else
            asm volatile("cp.async.wait_group 0;" ::: "memory");
        __syncthreads();
        if (c + 2 < NKC) load_chunk_g(sb, m0, n0, c + 2, (c + 2) % 3, tid);

        #pragma unroll
        for (int s = 0; s < 4; s++) {
            uint32_t kchunk = (uint32_t)(2 * s + chi);
            uint32_t acol = ((kchunk ^ aswz) * 16u);
            uint32_t bcol = ((kchunk ^ bswz) * 16u);

            uint32_t bf[2][4];
            #pragma unroll
            for (int nj2 = 0; nj2 < 2; nj2++)
                ldsm4(bf[nj2], sb + SBB(st) + (brow + nj2 * 16u) * 128u + bcol);

            uint32_t af[4][4];
            #pragma unroll
            for (int mi = 0; mi < 4; mi++)
                ldsm4(af[mi], sb + SA(st) + (arow + mi * 16u) * 128u + acol);

            #pragma unroll
            for (int mi = 0; mi < 4; mi++)
                #pragma unroll
                for (int nj = 0; nj < 4; nj++)
                    mma_fp16(acc[mi][nj], af[mi],
                             bf[nj >> 1][nj & 1], bf[nj >> 1][(nj & 1) + 2]);
        }
    }

    int b    = m0 >> 10;
    int mloc = m0 & 1023;
    int g  = lane >> 2;
    int cq = (lane & 3) * 2;
    #pragma unroll
    for (int mi = 0; mi < 4; mi++) {
        #pragma unroll
        for (int nj = 0; nj < 4; nj++) {
            int nb = n0 + wn0 + nj * 8 + cq;
            int mb = mloc + wm0 + mi * 16 + g;
            __half* d0 = g_ct + ((size_t)b * NN + nb) * MM + mb;
            d0[0]      = __float2half_rn(acc[mi][nj][0]);
            d0[MM]     = __float2half_rn(acc[mi][nj][1]);
            d0[8]      = __float2half_rn(acc[mi][nj][2]);
            d0[MM + 8] = __float2half_rn(acc[mi][nj][3]);
        }
    }
}

// ---------------------------------------------------------------------------
// K4: fused dcoef + (tap-gather ∘ upfirdn) + noise + bias + lrelu*sqrt2.
// fp16 tap planes in smem (24KB), half2 loads, all parity selects compile-time:
//   d  = (j>0)           -- half2 extraction offset
//   p0 = (j==1) ? 0 : 1  -- column coefficient phase
//   W0 = v0/2 - d ; e = 2+W0 ; es = e>>1
// Rows: t=u-1-i, a0=t&1, hS=(t+a0)>>1; fk[a0] @ row hS, fk[a0+2] @ row hS+1.
// Plane layout: 9 x 35 rows x 38 halves (19 uints), bank-conflict-free (19r).
// ---------------------------------------------------------------------------
#define PR  35
#define PCU 19
__global__ void __launch_bounds__(256, 4) k_fir(const float* __restrict__ f,
                                                const float* __restrict__ noise,
                                                const float* __restrict__ bias,
                                                float* __restrict__ out) {
    __shared__ uint32_t plu[9 * PR * PCU];   // 23.94KB fp16 tap planes
    __shared__ float fk[16];
    __shared__ float red[8];
    __shared__ float s_dco;

    int z = blockIdx.x;
    int b = z >> 9;
    int oc = z & 511;
    int tid = threadIdx.x;

    if (tid < 16) fk[tid] = f[tid] * 4.0f;

    // zero planes (5985 words)
    for (int i = tid; i < 9 * PR * PCU; i += 256) plu[i] = 0u;

    // dcoef partial (overlaps with zeroing)
    float part = 0.f;
    #pragma unroll
    for (int ic = tid; ic < IC; ic += 256) {
        float st = g_styles[b * IC + ic];
        part += st * st * g_wsum[oc * IC + ic];
    }
    #pragma unroll
    for (int o = 16; o; o >>= 1) part += __shfl_xor_sync(0xffffffffu, part, o);
    if ((tid & 31) == 0) red[tid >> 5] = part;
    __syncthreads();

    if (tid == 0) {
        float t = 0.f;
        #pragma unroll
        for (int i = 0; i < 8; i++) t += red[i];
        s_dco = rsqrtf(t + 1e-8f);
    }

    // fill plane interiors from g_ct: 1 uint4 load -> 4 word stores (8 halves)
    const uint4* csrc = (const uint4*)(g_ct + ((size_t)b * NN + (size_t)oc * 9) * MM);
    for (int i = tid; i < 1152; i += 256) {
        uint4 v = csrc[i];
        int tap = i >> 7, rem = i & 127;
        int h = rem >> 2, wq = rem & 3;
        int uidx = (tap * PR + h + 2) * PCU + 1 + 4 * wq;  // half base = row*38+2+8wq
        plu[uidx]     = v.x;
        plu[uidx + 1] = v.y;
        plu[uidx + 2] = v.z;
        plu[uidx + 3] = v.w;
    }
    __syncthreads();
    float dco = s_dco;

    int u  = tid & 63;
    int vh = (tid >> 6) << 3;     // v0/2, even (v0 = 16*(tid>>6))
    int v0 = vh << 1;

    float res[16];
    #pragma unroll
    for (int c = 0; c < 16; c++) res[c] = 0.f;

    #pragma unroll
    for (int tap = 0; tap < 9; tap++) {
        const int i  = tap / 3, j = tap % 3;
        const int d  = (j > 0) ? 1 : 0;          // compile-time
        const int p0 = (j == 1) ? 0 : 1;         // compile-time
        const int NU = (j == 1) ? 6 : 5;         // uints per row

        int t  = u - 1 - i;
        int a0 = t & 1;
        int hS = (t + a0) >> 1;
        int rbA = (tap * PR + hS + 2) * PCU;
        int rbB = rbA + PCU;
        int es  = (vh + 2 - d) >> 1;

        float2 fA[6], fB[6];
        #pragma unroll
        for (int m = 0; m < NU; m++) {
            uint32_t ua = plu[rbA + es + m];
            uint32_t ub = plu[rbB + es + m];
            fA[m] = __half22float2(*(const __half2*)&ua);
            fB[m] = __half22float2(*(const __half2*)&ub);
        }

        float rA[10], rB[10];
        #pragma unroll
        for (int l = 0; l < 10; l++) {
            const int hi = l + d;                // compile-time per l
            rA[l] = (hi & 1) ? fA[hi >> 1].y : fA[hi >> 1].x;
            rB[l] = (hi & 1) ? fB[hi >> 1].y : fB[hi >> 1].x;
        }

        float fa0 = fk[a0 * 4 + 0], fa1 = fk[a0 * 4 + 1];
        float fa2 = fk[a0 * 4 + 2], fa3 = fk[a0 * 4 + 3];
        float fb0 = fk[(a0 + 2) * 4 + 0], fb1 = fk[(a0 + 2) * 4 + 1];
        float fb2 = fk[(a0 + 2) * 4 + 2], fb3 = fk[(a0 + 2) * 4 + 3];

        if (p0 == 0) {
            #pragma unroll
            for (int k = 0; k < 8; k++) {
                res[2*k]   += fa0 * rA[k]     + fa2 * rA[k + 1]
                            + fb0 * rB[k]     + fb2 * rB[k + 1];
                res[2*k+1] += fa1 * rA[k + 1] + fa3 * rA[k + 2]
                            + fb1 * rB[k + 1] + fb3 * rB[k + 2];
            }
        } else {
            #pragma unroll
            for (int k = 0; k < 8; k++) {
                res[2*k]   += fa1 * rA[k] + fa3 * rA[k + 1]
                            + fb1 * rB[k] + fb3 * rB[k + 1];
                res[2*k+1] += fa0 * rA[k] + fa2 * rA[k + 1]
                            + fb0 * rB[k] + fb2 * rB[k + 1];
            }
        }
    }

    float bs = bias[oc];
    float* orow = out + (((size_t)(b * OC + oc) * RES) + u) * RES + v0;
    const float* nrow = noise + u * RES + v0;
    #pragma unroll
    for (int c = 0; c < 16; c++) {
        float v = res[c] * dco + nrow[c] + bs;
        v = (v > 0.f) ? v : 0.2f * v;
        orow[c] = v * 1.4142135623730951f;
    }
}

// ---------------------------------------------------------------------------
extern "C" void kernel_launch(void* const* d_in, const int* in_sizes, int n_in,
                              void* d_out, int out_size) {
    const float* x     = (const float*)d_in[0];
    const float* w     = (const float*)d_in[1];
    const float* aw    = (const float*)d_in[2];
    const float* ab    = (const float*)d_in[3];
    const float* cw    = (const float*)d_in[4];
    const float* bias  = (const float*)d_in[5];
    const float* noise = (const float*)d_in[6];
    const float* f     = (const float*)d_in[7];
    float* out = (float*)d_out;

    cudaFuncSetAttribute(k_gemm, cudaFuncAttributeMaxDynamicSharedMemorySize, SM_TOTAL_G);
    cudaFuncSetAttribute(k_fir, cudaFuncAttributePreferredSharedMemoryCarveout, 100);

    k_sw   <<<2048, 256>>>(w, aw, ab, cw);
    k_prep <<<2560, 256>>>(x, cw);
    k_gemm <<<dim3(NN / TN, MF / TM), 512, SM_TOTAL_G>>>();
    k_fir  <<<BATCH * OC, 256>>>(f, noise, bias, out);
}